// round 6
// baseline (speedup 1.0000x reference)
#include <cuda_runtime.h>
#include <cuda_bf16.h>
#include <math.h>

// Shapes: B=256, D=512, L=64, H=300
#define Bc 256
#define Dc 512
#define Lc 64
#define Hc 300
#define HP 320         // padded K for stage B (g1 rows)
#define NPAD 384       // padded column stride for decoder weight scratch
#define BD (Bc*Dc)

// ---------------- device scratch (no allocations allowed) ----------------
__device__ float g_g1T[64 * NPAD];        // [l][h]  = gen1_w[h][l], h<300 else 0
__device__ float g_g2T[HP * NPAD];        // [h][g]  = gen2_w[g][h], valid<300 else 0
__device__ float g_headp[Dc * NPAD];      // [d][g]  = head_w[d][g], g<300 else 0
__device__ float g_biasp[NPAD];           // gen2_b padded
__device__ float g_e1T[512 * 320];        // [k][j]  = enc1_w[j][k], j<300 else 0
__device__ float g_e2T[320 * 320];        // [k][j]  = enc2_w[j][k], pad 0
__device__ float g_zT[320 * 128];         // [k][j]  j<64: zm_w[j][k], else zv_w[j-64][k]

// ---------------- packed fp32x2 FMA (B300 full-rate fp32 path) ----------------
union F2U { float2 f; unsigned long long u; };
__device__ __forceinline__ float2 ffma2(float2 a, float2 b, float2 c) {
    F2U A, Bv, Cv; A.f = a; Bv.f = b; Cv.f = c;
    asm("fma.rn.f32x2 %0, %1, %2, %0;" : "+l"(Cv.u) : "l"(A.u), "l"(Bv.u));
    return Cv.f;
}

// ---------------- prep: pad + transpose all weights ----------------
__global__ void prep_kernel(const float* __restrict__ g1w,
                            const float* __restrict__ g2w,
                            const float* __restrict__ hw,
                            const float* __restrict__ g2b,
                            const float* __restrict__ e1w,
                            const float* __restrict__ e2w,
                            const float* __restrict__ zmw,
                            const float* __restrict__ zvw) {
    const int n1 = 64 * NPAD;
    const int n2 = n1 + HP * NPAD;
    const int n3 = n2 + Dc * NPAD;
    const int n4 = n3 + NPAD;
    const int n5 = n4 + 512 * 320;
    const int n6 = n5 + 320 * 320;
    const int n7 = n6 + 320 * 128;
    int i = blockIdx.x * blockDim.x + threadIdx.x;
    if (i >= n7) return;
    if (i < n1) {
        int l = i / NPAD, h = i % NPAD;
        g_g1T[i] = (h < Hc) ? g1w[h * Lc + l] : 0.f;
    } else if (i < n2) {
        int j = i - n1; int h = j / NPAD, g = j % NPAD;
        g_g2T[j] = (h < Hc && g < Hc) ? g2w[g * Hc + h] : 0.f;
    } else if (i < n3) {
        int j = i - n2; int d = j / NPAD, g = j % NPAD;
        g_headp[j] = (g < Hc) ? hw[d * Hc + g] : 0.f;
    } else if (i < n4) {
        int g = i - n3;
        g_biasp[g] = (g < Hc) ? g2b[g] : 0.f;
    } else if (i < n5) {
        int j = i - n4; int k = j / 320, c = j % 320;
        g_e1T[j] = (c < Hc) ? e1w[c * Dc + k] : 0.f;
    } else if (i < n6) {
        int j = i - n5; int k = j / 320, c = j % 320;
        g_e2T[j] = (c < Hc && k < Hc) ? e2w[c * Hc + k] : 0.f;
    } else {
        int j = i - n6; int k = j / 128, c = j % 128;
        float v = 0.f;
        if (k < Hc) v = (c < 64) ? zmw[c * Hc + k] : zvw[(c - 64) * Hc + k];
        g_zT[j] = v;
    }
}

// ---------------- fused encoder: 4 batch rows per CTA, 320 threads ----------------
#define RPC 4
__global__ __launch_bounds__(320)
void enc_kernel(const float* __restrict__ x, const float* __restrict__ eps,
                const float* __restrict__ e1b, const float* __restrict__ e2b,
                const float* __restrict__ zmb, const float* __restrict__ zvb,
                float* __restrict__ zm, float* __restrict__ zlv,
                float* __restrict__ z) {
    __shared__ float xs[RPC][512];
    __shared__ float h1s[RPC][320];
    __shared__ float h2s[RPC][320];
    __shared__ float zs[RPC][128];
    const int tid = threadIdx.x;
    const int b0 = blockIdx.x * RPC;

    for (int t = tid; t < RPC * 512; t += 320)
        xs[t >> 9][t & 511] = x[(b0 + (t >> 9)) * 512 + (t & 511)];
    __syncthreads();

    const int j = tid;   // 0..319
    {
        float bj = (j < Hc) ? e1b[j] : 0.f;
        float acc[RPC];
#pragma unroll
        for (int r = 0; r < RPC; r++) acc[r] = bj;
#pragma unroll 8
        for (int k = 0; k < 512; k++) {
            float w = g_e1T[k * 320 + j];
#pragma unroll
            for (int r = 0; r < RPC; r++) acc[r] += xs[r][k] * w;
        }
#pragma unroll
        for (int r = 0; r < RPC; r++) h1s[r][j] = fmaxf(acc[r], 0.f);
    }
    __syncthreads();
    {
        float bj = (j < Hc) ? e2b[j] : 0.f;
        float acc[RPC];
#pragma unroll
        for (int r = 0; r < RPC; r++) acc[r] = bj;
#pragma unroll 8
        for (int k = 0; k < 320; k++) {
            float w = g_e2T[k * 320 + j];
#pragma unroll
            for (int r = 0; r < RPC; r++) acc[r] += h1s[r][k] * w;
        }
#pragma unroll
        for (int r = 0; r < RPC; r++) h2s[r][j] = fmaxf(acc[r], 0.f);
    }
    __syncthreads();
    if (j < 128) {
        float bj = (j < 64) ? zmb[j] : zvb[j - 64];
        float acc[RPC];
#pragma unroll
        for (int r = 0; r < RPC; r++) acc[r] = bj;
#pragma unroll 8
        for (int k = 0; k < 320; k++) {
            float w = g_zT[k * 128 + j];
#pragma unroll
            for (int r = 0; r < RPC; r++) acc[r] += h2s[r][k] * w;
        }
#pragma unroll
        for (int r = 0; r < RPC; r++) zs[r][j] = acc[r];
    }
    __syncthreads();
    if (j < 64) {
#pragma unroll
        for (int r = 0; r < RPC; r++) {
            int b = b0 + r;
            float m = zs[r][j], lv = zs[r][j + 64];
            zm[b * 64 + j]  = m;
            zlv[b * 64 + j] = lv;
            z[b * 64 + j]   = m + eps[b * 64 + j] * expf(0.5f * lv);
        }
    }
}

// ---------------- decoder pass helpers (512 threads: tx=lane 0..31, ty=warp 0..15) ----
// Stage A: g1s[h][m] = relu(sum_l masked[l][m] * gen1_w[h][l]); pass covers 16*HT h-cols
template<int HT>
__device__ __forceinline__ void stageA_pass(const int h0, const int tx, const int ty,
                                            const int tid,
                                            const float* __restrict__ msf,
                                            float* __restrict__ wtb,
                                            float* __restrict__ g1s) {
    constexpr int PW = HT * 16;       // pass width in floats
    constexpr int QF = PW / 4;        // float4 per l-row
    for (int f = tid; f < 64 * QF; f += 512) {
        int l = f / QF;
        int h4 = f % QF;
        *(float4*)&wtb[l * PW + h4 * 4] = *(const float4*)&g_g1T[l * NPAD + h0 + h4 * 4];
    }
    __syncthreads();

    float2 c[HT][2];
#pragma unroll
    for (int i = 0; i < HT; i++) { c[i][0] = make_float2(0.f, 0.f); c[i][1] = make_float2(0.f, 0.f); }

#pragma unroll 8
    for (int l = 0; l < 64; l++) {
        float4 a = *(const float4*)&msf[l * 128 + tx * 4];      // per-lane, contiguous
        float2 ap[2] = {{a.x, a.y}, {a.z, a.w}};
        float bb[HT];                                            // broadcast within warp
        float4 b0 = *(const float4*)&wtb[l * PW + ty * HT];
        bb[0] = b0.x; bb[1] = b0.y; bb[2] = b0.z; bb[3] = b0.w;
        if constexpr (HT == 8) {
            float4 b1 = *(const float4*)&wtb[l * PW + ty * HT + 4];
            bb[4] = b1.x; bb[5] = b1.y; bb[6] = b1.z; bb[7] = b1.w;
        }
#pragma unroll
        for (int h = 0; h < HT; h++) {
            float2 bd = make_float2(bb[h], bb[h]);
            c[h][0] = ffma2(ap[0], bd, c[h][0]);
            c[h][1] = ffma2(ap[1], bd, c[h][1]);
        }
    }
#pragma unroll
    for (int h = 0; h < HT; h++) {
        int hg = h0 + ty * HT + h;
        float4 v;
        v.x = fmaxf(c[h][0].x, 0.f); v.y = fmaxf(c[h][0].y, 0.f);
        v.z = fmaxf(c[h][1].x, 0.f); v.w = fmaxf(c[h][1].y, 0.f);
        *(float4*)&g1s[hg * 128 + tx * 4] = v;
    }
    __syncthreads();
}

// Stage B: g2 + head contraction; pass covers 64*NW n-cols starting at g0
template<int NW>
__device__ __forceinline__ void stageB_pass(const int g0, const int tx, const int ty,
                                            const int tid, const int d0,
                                            const float* __restrict__ g1s,
                                            float* __restrict__ wtb,
                                            float* __restrict__ partial) {
    constexpr int PW = NW * 64;       // floats per k-row (128 or 64)
    constexpr int QF = PW / 4;        // float4 per k-row
    constexpr int NPF = (32 * QF + 511) / 512;  // prefetch f4 per thread (2 or 1)

    float2 c[8][NW];
#pragma unroll
    for (int i = 0; i < 8; i++)
#pragma unroll
        for (int jj = 0; jj < NW; jj++) c[i][jj] = make_float2(0.f, 0.f);

    float4 pre[NPF];
    // prologue: chunk 0 -> buf0
#pragma unroll
    for (int jj = 0; jj < NPF; jj++) {
        int f = tid + jj * 512; int k = f / QF; int n4 = f % QF;
        pre[jj] = *(const float4*)&g_g2T[k * NPAD + g0 + n4 * 4];
    }
#pragma unroll
    for (int jj = 0; jj < NPF; jj++) {
        int f = tid + jj * 512; int k = f / QF; int n4 = f % QF;
        *(float4*)&wtb[k * PW + n4 * 4] = pre[jj];
    }
    __syncthreads();

    for (int kc = 0; kc < 10; kc++) {
        const float* wb = wtb + (kc & 1) * (32 * PW);
        if (kc < 9) {
            int k0n = (kc + 1) * 32;
#pragma unroll
            for (int jj = 0; jj < NPF; jj++) {
                int f = tid + jj * 512; int k = f / QF; int n4 = f % QF;
                pre[jj] = *(const float4*)&g_g2T[(k0n + k) * NPAD + g0 + n4 * 4];
            }
        }
        int kb = kc * 32;
#pragma unroll 8
        for (int k = 0; k < 32; k++) {
            const float* g1r = &g1s[(kb + k) * 128 + ty * 8];   // broadcast within warp
            float4 a0 = *(const float4*)&g1r[0];
            float4 a1 = *(const float4*)&g1r[4];
            float aa[8] = {a0.x, a0.y, a0.z, a0.w, a1.x, a1.y, a1.z, a1.w};
            float2 bp[NW];
            if constexpr (NW == 2) {
                float4 b0 = *(const float4*)&wb[k * PW + tx * 4];
                bp[0] = make_float2(b0.x, b0.y); bp[1] = make_float2(b0.z, b0.w);
            } else {
                bp[0] = *(const float2*)&wb[k * PW + tx * 2];
            }
#pragma unroll
            for (int m = 0; m < 8; m++) {
                float2 ad = make_float2(aa[m], aa[m]);
#pragma unroll
                for (int np = 0; np < NW; np++) c[m][np] = ffma2(ad, bp[np], c[m][np]);
            }
        }
        if (kc < 9) {
            float* wo = wtb + ((kc + 1) & 1) * (32 * PW);
#pragma unroll
            for (int jj = 0; jj < NPF; jj++) {
                int f = tid + jj * 512; int k = f / QF; int n4 = f % QF;
                *(float4*)&wo[k * PW + n4 * 4] = pre[jj];
            }
        }
        __syncthreads();
    }

    // epilogue: relu(bias+acc) dotted with head_w row; owner-thread partials
#pragma unroll
    for (int m = 0; m < 8; m++) {
        int ml = ty * 8 + m;
        int d = d0 + ml;
        const float* hrow = &g_headp[d * NPAD + g0];
        float s = 0.f;
#pragma unroll
        for (int np = 0; np < NW; np++) {
            int nl = tx * (NW * 2) + 2 * np;
            float2 b2 = *(const float2*)&g_biasp[g0 + nl];
            float2 h2 = *(const float2*)&hrow[nl];
            float gx = fmaxf(c[m][np].x + b2.x, 0.f);
            float gy = fmaxf(c[m][np].y + b2.y, 0.f);
            s += gx * h2.x + gy * h2.y;
        }
        partial[ml * 32 + tx] += s;
    }
}

// ---------------- fused decoder ----------------
// grid = 1024 CTAs, each owns 128 rows (one b, d in [d0, d0+128)), 512 threads.
__global__ __launch_bounds__(512, 1)
void decoder_kernel(const float* __restrict__ W,
                    const float* __restrict__ z_all,
                    const float* __restrict__ head_b,
                    float* __restrict__ xmean) {
    extern __shared__ float sm[];
    float* g1s = sm;                  // 40960 floats (320 x 128)
    float* msf = sm + 40960;          // 8192 floats (masked, later partials 128x32)
    float* wtb = sm + 40960 + 8192;   // 8192 floats (weights, dbuf)

    const int tid = threadIdx.x;
    const int tx = tid & 31;          // lane
    const int ty = tid >> 5;          // warp id 0..15
    const int r0 = blockIdx.x * 128;
    const int b = r0 >> 9;
    const int d0 = r0 & 511;
    const float* zrow = z_all + b * Lc;

    // masked[l][m] = z[b][l] * W[d0+m][l]  (transposed into smem)
    for (int t = tid; t < 2048; t += 512) {
        int m = t >> 4;
        int l4 = t & 15;
        float4 w4 = *(const float4*)&W[(d0 + m) * Lc + l4 * 4];
        float4 z4 = *(const float4*)&zrow[l4 * 4];
        int base = (l4 * 4) * 128 + m;
        msf[base]       = w4.x * z4.x;
        msf[base + 128] = w4.y * z4.y;
        msf[base + 256] = w4.z * z4.z;
        msf[base + 384] = w4.w * z4.w;
    }
    __syncthreads();

    // stage A: 128 + 128 + 64 h-columns = 320 rows of g1s
    stageA_pass<8>(0,   tx, ty, tid, msf, wtb, g1s);
    stageA_pass<8>(128, tx, ty, tid, msf, wtb, g1s);
    stageA_pass<4>(256, tx, ty, tid, msf, wtb, g1s);

    // zero partial sums (reuse msf region: partial[128][32])
    for (int t = tid; t < 4096; t += 512) msf[t] = 0.f;
    __syncthreads();

    // stage B: 128 + 128 + 64 n-columns = 320 (covers N=300)
    stageB_pass<2>(0,   tx, ty, tid, d0, g1s, wtb, msf);
    stageB_pass<2>(128, tx, ty, tid, d0, g1s, wtb, msf);
    stageB_pass<1>(256, tx, ty, tid, d0, g1s, wtb, msf);
    __syncthreads();

    if (tid < 128) {
        float s = head_b[d0 + tid];
#pragma unroll
        for (int t = 0; t < 32; t++) s += msf[tid * 32 + t];
        xmean[r0 + tid] = s;
    }
}

// ---------------- launch ----------------
extern "C" void kernel_launch(void* const* d_in, const int* in_sizes, int n_in,
                              void* d_out, int out_size) {
    const float* x      = (const float*)d_in[0];
    const float* eps    = (const float*)d_in[1];
    const float* W      = (const float*)d_in[2];
    const float* enc1_w = (const float*)d_in[3];
    const float* enc1_b = (const float*)d_in[4];
    const float* enc2_w = (const float*)d_in[5];
    const float* enc2_b = (const float*)d_in[6];
    const float* zm_w   = (const float*)d_in[7];
    const float* zm_b   = (const float*)d_in[8];
    const float* zv_w   = (const float*)d_in[9];
    const float* zv_b   = (const float*)d_in[10];
    const float* gen1_w = (const float*)d_in[11];
    const float* gen2_w = (const float*)d_in[12];
    const float* gen2_b = (const float*)d_in[13];
    const float* head_w = (const float*)d_in[14];
    const float* head_b = (const float*)d_in[15];

    float* out   = (float*)d_out;
    float* xmean = out;                    // [256*512]
    float* z     = out + BD;               // [256*64]
    float* zm    = out + BD + Bc * Lc;     // [256*64]
    float* zlv   = out + BD + 2 * Bc * Lc; // [256*64]

    // weight prep (pad + transpose everything)
    {
        int tot = 64 * NPAD + HP * NPAD + Dc * NPAD + NPAD
                + 512 * 320 + 320 * 320 + 320 * 128;
        prep_kernel<<<(tot + 255) / 256, 256>>>(gen1_w, gen2_w, head_w, gen2_b,
                                                enc1_w, enc2_w, zm_w, zv_w);
    }

    // fused encoder (one kernel: enc1 -> enc2 -> zm/zv -> z)
    enc_kernel<<<Bc / RPC, 320>>>(x, eps, enc1_b, enc2_b, zm_b, zv_b, zm, zlv, z);

    // fused decoder
    const int smem_bytes = (40960 + 8192 + 8192) * 4;  // 229376 B
    cudaFuncSetAttribute(decoder_kernel, cudaFuncAttributeMaxDynamicSharedMemorySize,
                         smem_bytes);
    decoder_kernel<<<BD / 128, 512, smem_bytes>>>(W, z, head_b, xmean);
}

// round 10
// speedup vs baseline: 2.5377x; 2.5377x over previous
#include <cuda_runtime.h>
#include <math.h>
#include <stdint.h>

// Shapes: B=256, D=512, L=64, H=300
#define Bc 256
#define Dc 512
#define Lc 64
#define Hc 300
#define BD (Bc*Dc)

// ---------------- device scratch ----------------
__device__ float g_e1T[512 * 320];     // encoder weights transposed/padded
__device__ float g_e2T[320 * 320];
__device__ float g_zT[320 * 128];
__device__ float g_g1F[20480];         // gen1 B-fragments: [ks(8)][nt(40)][lane(32)][2]
__device__ float g_g2F[102400];        // gen2 B-fragments: [ksg(40)][nt(40)][lane(32)][2]
__device__ float g_headp[Dc * 320];    // head_w padded [d][g]
__device__ float g_biasp[320];         // gen2_b padded

// ---------------- helpers ----------------
__device__ __forceinline__ float to_tf32(float x) {
    uint32_t o; asm("cvt.rna.tf32.f32 %0, %1;" : "=r"(o) : "f"(x)); return __uint_as_float(o);
}
__device__ __forceinline__ uint32_t smem_u32(const void* p) {
    uint32_t a;
    asm("{ .reg .u64 t; cvta.to.shared.u64 t, %1; cvt.u32.u64 %0, t; }" : "=r"(a) : "l"(p));
    return a;
}
__device__ __forceinline__ void mma_tf32(float* c, uint32_t a0, uint32_t a1, uint32_t a2,
                                         uint32_t a3, uint32_t b0, uint32_t b1) {
    asm volatile(
        "mma.sync.aligned.m16n8k8.row.col.f32.tf32.tf32.f32 "
        "{%0,%1,%2,%3}, {%4,%5,%6,%7}, {%8,%9}, {%0,%1,%2,%3};"
        : "+f"(c[0]), "+f"(c[1]), "+f"(c[2]), "+f"(c[3])
        : "r"(a0), "r"(a1), "r"(a2), "r"(a3), "r"(b0), "r"(b1));
}

// ---------------- prep: transpose/pad + tf32-round + pack B fragments ----------------
__global__ void prep_kernel(const float* __restrict__ g1w, const float* __restrict__ g2w,
                            const float* __restrict__ hw,  const float* __restrict__ g2b,
                            const float* __restrict__ e1w, const float* __restrict__ e2w,
                            const float* __restrict__ zmw, const float* __restrict__ zvw) {
    const int n1 = 512 * 320;            // e1T
    const int n2 = n1 + 320 * 320;       // e2T
    const int n3 = n2 + 320 * 128;       // zT
    const int n4 = n3 + 20480;           // g1F
    const int n5 = n4 + 102400;          // g2F
    const int n6 = n5 + Dc * 320;        // headp
    const int n7 = n6 + 320;             // biasp
    int i = blockIdx.x * blockDim.x + threadIdx.x;
    if (i >= n7) return;
    if (i < n1) { int k = i / 320, c = i % 320; g_e1T[i] = (c < Hc) ? e1w[c * Dc + k] : 0.f; }
    else if (i < n2) { int j = i - n1; int k = j / 320, c = j % 320;
        g_e2T[j] = (c < Hc && k < Hc) ? e2w[c * Hc + k] : 0.f; }
    else if (i < n3) { int j = i - n2; int k = j / 128, c = j % 128;
        float v = 0.f; if (k < Hc) v = (c < 64) ? zmw[c * Hc + k] : zvw[(c - 64) * Hc + k];
        g_zT[j] = v; }
    else if (i < n4) { int j = i - n3;
        int ks = j / 2560, r = j % 2560;
        int nt = r / 64, r2 = r % 64, lane = r2 >> 1, s = r2 & 1;
        int k = ks * 8 + (lane & 3) + s * 4;
        int n = nt * 8 + (lane >> 2);
        g_g1F[j] = (n < Hc) ? to_tf32(g1w[n * Lc + k]) : 0.f; }
    else if (i < n5) { int j = i - n4;
        int ksg = j / 2560, r = j % 2560;
        int nt = r / 64, r2 = r % 64, lane = r2 >> 1, s = r2 & 1;
        int k = ksg * 8 + (lane & 3) + s * 4;
        int n = nt * 8 + (lane >> 2);
        g_g2F[j] = (k < Hc && n < Hc) ? to_tf32(g2w[n * Hc + k]) : 0.f; }
    else if (i < n6) { int j = i - n5; int d = j / 320, g = j % 320;
        g_headp[j] = (g < Hc) ? hw[d * Hc + g] : 0.f; }
    else { int g = i - n6; g_biasp[g] = (g < Hc) ? g2b[g] : 0.f; }
}

// ---------------- fused encoder: 4 batch rows per CTA, 320 threads (fp32, exact) ----------------
#define RPC 4
__global__ __launch_bounds__(320)
void enc_kernel(const float* __restrict__ x, const float* __restrict__ eps,
                const float* __restrict__ e1b, const float* __restrict__ e2b,
                const float* __restrict__ zmb, const float* __restrict__ zvb,
                float* __restrict__ zm, float* __restrict__ zlv, float* __restrict__ z) {
    __shared__ float xs[RPC][512];
    __shared__ float h1s[RPC][320];
    __shared__ float h2s[RPC][320];
    __shared__ float zs[RPC][128];
    const int tid = threadIdx.x;
    const int b0 = blockIdx.x * RPC;

    for (int t = tid; t < RPC * 512; t += 320)
        xs[t >> 9][t & 511] = x[(b0 + (t >> 9)) * 512 + (t & 511)];
    __syncthreads();

    const int j = tid;
    {
        float bj = (j < Hc) ? e1b[j] : 0.f;
        float acc[RPC];
#pragma unroll
        for (int r = 0; r < RPC; r++) acc[r] = bj;
#pragma unroll 8
        for (int k = 0; k < 512; k++) {
            float w = g_e1T[k * 320 + j];
#pragma unroll
            for (int r = 0; r < RPC; r++) acc[r] += xs[r][k] * w;
        }
#pragma unroll
        for (int r = 0; r < RPC; r++) h1s[r][j] = fmaxf(acc[r], 0.f);
    }
    __syncthreads();
    {
        float bj = (j < Hc) ? e2b[j] : 0.f;
        float acc[RPC];
#pragma unroll
        for (int r = 0; r < RPC; r++) acc[r] = bj;
#pragma unroll 8
        for (int k = 0; k < 320; k++) {
            float w = g_e2T[k * 320 + j];
#pragma unroll
            for (int r = 0; r < RPC; r++) acc[r] += h1s[r][k] * w;
        }
#pragma unroll
        for (int r = 0; r < RPC; r++) h2s[r][j] = fmaxf(acc[r], 0.f);
    }
    __syncthreads();
    if (j < 128) {
        float bj = (j < 64) ? zmb[j] : zvb[j - 64];
        float acc[RPC];
#pragma unroll
        for (int r = 0; r < RPC; r++) acc[r] = bj;
#pragma unroll 8
        for (int k = 0; k < 320; k++) {
            float w = g_zT[k * 128 + j];
#pragma unroll
            for (int r = 0; r < RPC; r++) acc[r] += h2s[r][k] * w;
        }
#pragma unroll
        for (int r = 0; r < RPC; r++) zs[r][j] = acc[r];
    }
    __syncthreads();
    if (j < 64) {
#pragma unroll
        for (int r = 0; r < RPC; r++) {
            int b = b0 + r;
            float m = zs[r][j], lv = zs[r][j + 64];
            zm[b * 64 + j] = m;
            zlv[b * 64 + j] = lv;
            z[b * 64 + j] = m + eps[b * 64 + j] * expf(0.5f * lv);
        }
    }
}

// ---------------- cp.async chunk streamer ----------------
// one chunk = 2 k-steps x 40 n-tiles x 32 lanes x 2 = 5120 floats (20KB)
__device__ __forceinline__ void issue_chunk(const float* gF, int ck, float* bbuf,
                                            int which, int tid) {
    const float4* src = (const float4*)(gF + ck * 5120) + tid;
    uint32_t dst = smem_u32(bbuf + which * 5120) + (uint32_t)tid * 16;
#pragma unroll
    for (int j = 0; j < 5; j++) {
        asm volatile("cp.async.cg.shared.global [%0], [%1], 16;"
                     :: "r"(dst + j * 256 * 16), "l"(src + j * 256));
    }
    asm volatile("cp.async.commit_group;" ::: "memory");
}

// ---------------- chunked warp-MMA GEMM ----------------
// C[mt][nt][4] accumulators; A in smem (stride AS, AS mod 32 == 4);
// B fragments streamed from gF (frag-packed) through double-buffered bbuf.
__device__ __forceinline__ void gemm_chunks(float (&C)[4][10][4], const float* gF,
                                            int nchunks, const float* Arow, int AS,
                                            float* bbuf, int tid, int lane, int wn) {
    issue_chunk(gF, 0, bbuf, 0, tid);
    for (int ck = 0; ck < nchunks; ck++) {
        if (ck + 1 < nchunks) {
            issue_chunk(gF, ck + 1, bbuf, (ck + 1) & 1, tid);
            asm volatile("cp.async.wait_group 1;" ::: "memory");
        } else {
            asm volatile("cp.async.wait_group 0;" ::: "memory");
        }
        __syncthreads();
        const float* bb = bbuf + (ck & 1) * 5120 + (wn * 10 * 32 + lane) * 2;
#pragma unroll
        for (int kt = 0; kt < 2; kt++) {
            const int ks = ck * 2 + kt;
            uint32_t b0[10], b1[10];
#pragma unroll
            for (int nt = 0; nt < 10; nt++) {
                float2 bv = *(const float2*)(bb + kt * 2560 + nt * 64);
                b0[nt] = __float_as_uint(bv.x);
                b1[nt] = __float_as_uint(bv.y);
            }
#pragma unroll
            for (int mt = 0; mt < 4; mt++) {
                const float* ap = Arow + mt * 16 * AS + ks * 8;
                uint32_t a0 = __float_as_uint(ap[0]);
                uint32_t a1 = __float_as_uint(ap[8 * AS]);
                uint32_t a2 = __float_as_uint(ap[4]);
                uint32_t a3 = __float_as_uint(ap[8 * AS + 4]);
#pragma unroll
                for (int nt = 0; nt < 10; nt++)
                    mma_tf32(C[mt][nt], a0, a1, a2, a3, b0[nt], b1[nt]);
            }
        }
        __syncthreads();
    }
}

// ---------------- fused decoder (tf32 mma.sync) ----------------
// grid = 1024 CTAs x 256 threads (8 warps, 2m x 4n; warp tile 64x80).
// smem: g1s[128x324] (msA[128x68] aliases its start) | bbuf 2x5120 | partial[128x17]
__global__ __launch_bounds__(256, 1)
void decoder_kernel(const float* __restrict__ W, const float* __restrict__ z_all,
                    const float* __restrict__ head_b, float* __restrict__ xmean) {
    extern __shared__ float sm[];
    float* g1s = sm;                    // 41472 floats
    float* msA = sm;                    // aliases g1s start (8704 floats, stage A only)
    float* bbuf = sm + 41472;           // 10240 floats
    float* partial = sm + 51712;        // 2176 floats (128 x 17)

    const int tid = threadIdx.x;
    const int lane = tid & 31;
    const int wid = tid >> 5;
    const int wm = wid & 1;             // m-warp: rows wm*64..+63
    const int wn = wid >> 1;            // n-warp: cols wn*80..+79
    const int g = lane >> 2;            // groupID
    const int tg = lane & 3;            // threadID_in_group
    const int r0 = blockIdx.x * 128;
    const int b = r0 >> 9;
    const int d0 = r0 & 511;
    const float* zrow = z_all + b * Lc;

    // ---- masked A = tf32(z * W), row-major stride 68 ----
    for (int t = tid; t < 2048; t += 256) {
        int m = t >> 4, k4 = t & 15;
        float4 w4 = *(const float4*)&W[(d0 + m) * Lc + k4 * 4];
        float4 z4 = *(const float4*)&zrow[k4 * 4];
        float4 v;
        v.x = to_tf32(w4.x * z4.x); v.y = to_tf32(w4.y * z4.y);
        v.z = to_tf32(w4.z * z4.z); v.w = to_tf32(w4.w * z4.w);
        *(float4*)&msA[m * 68 + k4 * 4] = v;
    }
    __syncthreads();

    float C[4][10][4];

    // ---- stage A: g1 = relu(masked @ gen1^T), K=64 (4 chunks) ----
#pragma unroll
    for (int mt = 0; mt < 4; mt++)
#pragma unroll
        for (int nt = 0; nt < 10; nt++)
#pragma unroll
            for (int q = 0; q < 4; q++) C[mt][nt][q] = 0.f;

    const float* ArowA = msA + (wm * 64 + g) * 68 + tg;
    gemm_chunks(C, g_g1F, 4, ArowA, 68, bbuf, tid, lane, wn);
    // gemm ends with __syncthreads: all warps done reading msA; safe to overwrite.

#pragma unroll
    for (int mt = 0; mt < 4; mt++) {
        int rL = wm * 64 + mt * 16 + g;
#pragma unroll
        for (int nt = 0; nt < 10; nt++) {
            int n0 = wn * 80 + nt * 8 + 2 * tg;
            float2 vL, vH;
            vL.x = to_tf32(fmaxf(C[mt][nt][0], 0.f));
            vL.y = to_tf32(fmaxf(C[mt][nt][1], 0.f));
            vH.x = to_tf32(fmaxf(C[mt][nt][2], 0.f));
            vH.y = to_tf32(fmaxf(C[mt][nt][3], 0.f));
            *(float2*)&g1s[rL * 324 + n0] = vL;
            *(float2*)&g1s[(rL + 8) * 324 + n0] = vH;
        }
    }
    __syncthreads();

    // ---- stage B: g2 = relu(g1 @ gen2^T + b) fused with head dot, K=320 (20 chunks) ----
#pragma unroll
    for (int mt = 0; mt < 4; mt++)
#pragma unroll
        for (int nt = 0; nt < 10; nt++)
#pragma unroll
            for (int q = 0; q < 4; q++) C[mt][nt][q] = 0.f;

    const float* ArowB = g1s + (wm * 64 + g) * 324 + tg;
    gemm_chunks(C, g_g2F, 20, ArowB, 324, bbuf, tid, lane, wn);

#pragma unroll
    for (int mt = 0; mt < 4; mt++) {
        int rL = wm * 64 + mt * 16 + g;
        int rH = rL + 8;
        float aL = 0.f, aH = 0.f;
#pragma unroll
        for (int nt = 0; nt < 10; nt++) {
            int n0 = wn * 80 + nt * 8 + 2 * tg;
            float2 bi = *(const float2*)&g_biasp[n0];
            float2 hL = *(const float2*)&g_headp[(d0 + rL) * 320 + n0];
            float2 hH = *(const float2*)&g_headp[(d0 + rH) * 320 + n0];
            aL += fmaxf(C[mt][nt][0] + bi.x, 0.f) * hL.x
                + fmaxf(C[mt][nt][1] + bi.y, 0.f) * hL.y;
            aH += fmaxf(C[mt][nt][2] + bi.x, 0.f) * hH.x
                + fmaxf(C[mt][nt][3] + bi.y, 0.f) * hH.y;
        }
        partial[rL * 17 + wn * 4 + tg] = aL;
        partial[rH * 17 + wn * 4 + tg] = aH;
    }
    __syncthreads();

    if (tid < 128) {
        float s = head_b[d0 + tid];
#pragma unroll
        for (int j = 0; j < 16; j++) s += partial[tid * 17 + j];
        xmean[r0 + tid] = s;
    }
}

// ---------------- launch ----------------
extern "C" void kernel_launch(void* const* d_in, const int* in_sizes, int n_in,
                              void* d_out, int out_size) {
    const float* x      = (const float*)d_in[0];
    const float* eps    = (const float*)d_in[1];
    const float* W      = (const float*)d_in[2];
    const float* enc1_w = (const float*)d_in[3];
    const float* enc1_b = (const float*)d_in[4];
    const float* enc2_w = (const float*)d_in[5];
    const float* enc2_b = (const float*)d_in[6];
    const float* zm_w   = (const float*)d_in[7];
    const float* zm_b   = (const float*)d_in[8];
    const float* zv_w   = (const float*)d_in[9];
    const float* zv_b   = (const float*)d_in[10];
    const float* gen1_w = (const float*)d_in[11];
    const float* gen2_w = (const float*)d_in[12];
    const float* gen2_b = (const float*)d_in[13];
    const float* head_w = (const float*)d_in[14];
    const float* head_b = (const float*)d_in[15];

    float* out   = (float*)d_out;
    float* xmean = out;
    float* z     = out + BD;
    float* zm    = out + BD + Bc * Lc;
    float* zlv   = out + BD + 2 * Bc * Lc;

    {
        int tot = 512 * 320 + 320 * 320 + 320 * 128 + 20480 + 102400 + Dc * 320 + 320;
        prep_kernel<<<(tot + 255) / 256, 256>>>(gen1_w, gen2_w, head_w, gen2_b,
                                                enc1_w, enc2_w, zm_w, zv_w);
    }

    enc_kernel<<<Bc / RPC, 320>>>(x, eps, enc1_b, enc2_b, zm_b, zv_b, zm, zlv, z);

    const int smem_bytes = (41472 + 10240 + 2176) * 4;   // 215,552 B
    cudaFuncSetAttribute(decoder_kernel, cudaFuncAttributeMaxDynamicSharedMemorySize,
                         smem_bytes);
    decoder_kernel<<<BD / 128, 256, smem_bytes>>>(W, z, head_b, xmean);
}

// round 11
// speedup vs baseline: 3.7091x; 1.4616x over previous
#include <cuda_runtime.h>
#include <math.h>
#include <stdint.h>

// Shapes: B=256, D=512, L=64, H=300
#define Bc 256
#define Dc 512
#define Lc 64
#define Hc 300
#define BD (Bc*Dc)

// ---------------- device scratch ----------------
__device__ float g_e1T[512 * 320];                 // encoder weights transposed/padded
__device__ float g_e2T[320 * 320];
__device__ float g_zT[320 * 128];
__device__ __align__(16) float    g_g1F[20480];    // gen1 tf32 frags: [ks8(8)][nt(40)][lane(32)][2]
__device__ __align__(16) uint32_t g_g2Fb[51200];   // gen2 bf16 frags: [ks16(20)][nt(40)][lane(32)][2 regs]
__device__ float g_headp[Dc * 320];                // head_w padded [d][g]
__device__ float g_biasp[320];                     // gen2_b padded

// ---------------- helpers ----------------
__device__ __forceinline__ float to_tf32(float x) {
    uint32_t o; asm("cvt.rna.tf32.f32 %0, %1;" : "=r"(o) : "f"(x)); return __uint_as_float(o);
}
__device__ __forceinline__ uint32_t pack_bf16x2(float hi, float lo) {
    uint32_t d; asm("cvt.rn.bf16x2.f32 %0, %1, %2;" : "=r"(d) : "f"(hi), "f"(lo)); return d;
}
__device__ __forceinline__ uint32_t smem_u32(const void* p) {
    uint32_t a;
    asm("{ .reg .u64 t; cvta.to.shared.u64 t, %1; cvt.u32.u64 %0, t; }" : "=r"(a) : "l"(p));
    return a;
}
__device__ __forceinline__ void mma_tf32(float* c, uint32_t a0, uint32_t a1, uint32_t a2,
                                         uint32_t a3, uint32_t b0, uint32_t b1) {
    asm volatile(
        "mma.sync.aligned.m16n8k8.row.col.f32.tf32.tf32.f32 "
        "{%0,%1,%2,%3}, {%4,%5,%6,%7}, {%8,%9}, {%0,%1,%2,%3};"
        : "+f"(c[0]), "+f"(c[1]), "+f"(c[2]), "+f"(c[3])
        : "r"(a0), "r"(a1), "r"(a2), "r"(a3), "r"(b0), "r"(b1));
}
__device__ __forceinline__ void mma_bf16(float* c, uint32_t a0, uint32_t a1, uint32_t a2,
                                         uint32_t a3, uint32_t b0, uint32_t b1) {
    asm volatile(
        "mma.sync.aligned.m16n8k16.row.col.f32.bf16.bf16.f32 "
        "{%0,%1,%2,%3}, {%4,%5,%6,%7}, {%8,%9}, {%0,%1,%2,%3};"
        : "+f"(c[0]), "+f"(c[1]), "+f"(c[2]), "+f"(c[3])
        : "r"(a0), "r"(a1), "r"(a2), "r"(a3), "r"(b0), "r"(b1));
}

// ---------------- prep: transpose/pad + round + pack MMA fragments ----------------
__global__ void prep_kernel(const float* __restrict__ g1w, const float* __restrict__ g2w,
                            const float* __restrict__ hw,  const float* __restrict__ g2b,
                            const float* __restrict__ e1w, const float* __restrict__ e2w,
                            const float* __restrict__ zmw, const float* __restrict__ zvw) {
    const int n1 = 512 * 320;            // e1T
    const int n2 = n1 + 320 * 320;       // e2T
    const int n3 = n2 + 320 * 128;       // zT
    const int n4 = n3 + 20480;           // g1F (tf32 frags)
    const int n5 = n4 + 51200;           // g2Fb (bf16 frags)
    const int n6 = n5 + Dc * 320;        // headp
    const int n7 = n6 + 320;             // biasp
    int i = blockIdx.x * blockDim.x + threadIdx.x;
    if (i >= n7) return;
    if (i < n1) { int k = i / 320, c = i % 320; g_e1T[i] = (c < Hc) ? e1w[c * Dc + k] : 0.f; }
    else if (i < n2) { int j = i - n1; int k = j / 320, c = j % 320;
        g_e2T[j] = (c < Hc && k < Hc) ? e2w[c * Hc + k] : 0.f; }
    else if (i < n3) { int j = i - n2; int k = j / 128, c = j % 128;
        float v = 0.f; if (k < Hc) v = (c < 64) ? zmw[c * Hc + k] : zvw[(c - 64) * Hc + k];
        g_zT[j] = v; }
    else if (i < n4) { int j = i - n3;
        int ks = j / 2560, r = j % 2560;
        int nt = r / 64, r2 = r % 64, lane = r2 >> 1, s = r2 & 1;
        int k = ks * 8 + (lane & 3) + s * 4;
        int n = nt * 8 + (lane >> 2);
        g_g1F[j] = (n < Hc) ? to_tf32(g1w[n * Lc + k]) : 0.f; }
    else if (i < n5) { int j = i - n4;
        int ks16 = j / 2560, r = j % 2560;
        int nt = r / 64, r2 = r % 64, lane = r2 >> 1, rr = r2 & 1;
        int g = lane >> 2, tg = lane & 3;
        int k = ks16 * 16 + tg * 2 + rr * 8;
        int n = nt * 8 + g;
        float lo = (n < Hc && k < Hc) ? g2w[n * Hc + k] : 0.f;
        float hi = (n < Hc && (k + 1) < Hc) ? g2w[n * Hc + k + 1] : 0.f;
        g_g2Fb[j] = pack_bf16x2(hi, lo); }
    else if (i < n6) { int j = i - n5; int d = j / 320, g = j % 320;
        g_headp[j] = (g < Hc) ? hw[d * Hc + g] : 0.f; }
    else { int g = i - n6; g_biasp[g] = (g < Hc) ? g2b[g] : 0.f; }
}

// ---------------- fused encoder: 4 batch rows per CTA, 320 threads (fp32, exact) ----------------
#define RPC 4
__global__ __launch_bounds__(320)
void enc_kernel(const float* __restrict__ x, const float* __restrict__ eps,
                const float* __restrict__ e1b, const float* __restrict__ e2b,
                const float* __restrict__ zmb, const float* __restrict__ zvb,
                float* __restrict__ zm, float* __restrict__ zlv, float* __restrict__ z) {
    __shared__ float xs[RPC][512];
    __shared__ float h1s[RPC][320];
    __shared__ float h2s[RPC][320];
    __shared__ float zs[RPC][128];
    const int tid = threadIdx.x;
    const int b0 = blockIdx.x * RPC;

    for (int t = tid; t < RPC * 512; t += 320)
        xs[t >> 9][t & 511] = x[(b0 + (t >> 9)) * 512 + (t & 511)];
    __syncthreads();

    const int j = tid;
    {
        float bj = (j < Hc) ? e1b[j] : 0.f;
        float acc[RPC];
#pragma unroll
        for (int r = 0; r < RPC; r++) acc[r] = bj;
#pragma unroll 8
        for (int k = 0; k < 512; k++) {
            float w = g_e1T[k * 320 + j];
#pragma unroll
            for (int r = 0; r < RPC; r++) acc[r] += xs[r][k] * w;
        }
#pragma unroll
        for (int r = 0; r < RPC; r++) h1s[r][j] = fmaxf(acc[r], 0.f);
    }
    __syncthreads();
    {
        float bj = (j < Hc) ? e2b[j] : 0.f;
        float acc[RPC];
#pragma unroll
        for (int r = 0; r < RPC; r++) acc[r] = bj;
#pragma unroll 8
        for (int k = 0; k < 320; k++) {
            float w = g_e2T[k * 320 + j];
#pragma unroll
            for (int r = 0; r < RPC; r++) acc[r] += h1s[r][k] * w;
        }
#pragma unroll
        for (int r = 0; r < RPC; r++) h2s[r][j] = fmaxf(acc[r], 0.f);
    }
    __syncthreads();
    if (j < 128) {
        float bj = (j < 64) ? zmb[j] : zvb[j - 64];
        float acc[RPC];
#pragma unroll
        for (int r = 0; r < RPC; r++) acc[r] = bj;
#pragma unroll 8
        for (int k = 0; k < 320; k++) {
            float w = g_zT[k * 128 + j];
#pragma unroll
            for (int r = 0; r < RPC; r++) acc[r] += h2s[r][k] * w;
        }
#pragma unroll
        for (int r = 0; r < RPC; r++) zs[r][j] = acc[r];
    }
    __syncthreads();
    if (j < 64) {
#pragma unroll
        for (int r = 0; r < RPC; r++) {
            int b = b0 + r;
            float m = zs[r][j], lv = zs[r][j + 64];
            zm[b * 64 + j] = m;
            zlv[b * 64 + j] = lv;
            z[b * 64 + j] = m + eps[b * 64 + j] * expf(0.5f * lv);
        }
    }
}

// ---------------- cp.async: one 40KB chunk (10240 x 4B) = 10 x 16B per thread ----------------
__device__ __forceinline__ void issue_chunk40(const void* src, float* dstf, int tid) {
    const float4* s = (const float4*)src + tid;
    uint32_t d = smem_u32(dstf) + (uint32_t)tid * 16;
#pragma unroll
    for (int j = 0; j < 10; j++) {
        asm volatile("cp.async.cg.shared.global [%0], [%1], 16;"
                     :: "r"(d + j * 256 * 16), "l"(s + j * 256));
    }
    asm volatile("cp.async.commit_group;" ::: "memory");
}
#define CP_WAIT_ALL() asm volatile("cp.async.wait_group 0;" ::: "memory")

// ---------------- fused decoder: stage A tf32, stage B bf16 ----------------
// grid = 1024 CTAs x 256 threads (8 warps, 2m x 4n; warp tile 64x80).
// smem floats: g1s(bf16 128x328 = 20992f) | msA(128x68 = 8704f) | bbuf(2x10240f) | partial(128x17)
__global__ __launch_bounds__(256, 1)
void decoder_kernel(const float* __restrict__ W, const float* __restrict__ z_all,
                    const float* __restrict__ head_b, float* __restrict__ xmean) {
    extern __shared__ float sm[];
    uint16_t* g1s = (uint16_t*)sm;            // 128 x 328 bf16 (stride 328 halves)
    float* msA = sm + 20992;                  // stage A input, stride 68
    float* bbuf = sm + 20992 + 8704;          // 2 x 10240 floats
    float* partial = bbuf + 20480;            // 128 x 17

    const int tid = threadIdx.x;
    const int lane = tid & 31;
    const int wid = tid >> 5;
    const int wm = wid & 1;
    const int wn = wid >> 1;
    const int g = lane >> 2;
    const int tg = lane & 3;
    const int r0 = blockIdx.x * 128;
    const int b = r0 >> 9;
    const int d0 = r0 & 511;
    const float* zrow = z_all + b * Lc;

    // prefetch stage A weight chunk 0 immediately (overlaps masked fill)
    issue_chunk40(g_g1F, bbuf, tid);

    // ---- masked A = tf32(z * W), row-major stride 68 ----
    for (int t = tid; t < 2048; t += 256) {
        int m = t >> 4, k4 = t & 15;
        float4 w4 = *(const float4*)&W[(d0 + m) * Lc + k4 * 4];
        float4 z4 = *(const float4*)&zrow[k4 * 4];
        float4 v;
        v.x = to_tf32(w4.x * z4.x); v.y = to_tf32(w4.y * z4.y);
        v.z = to_tf32(w4.z * z4.z); v.w = to_tf32(w4.w * z4.w);
        *(float4*)&msA[m * 68 + k4 * 4] = v;
    }

    float C[4][10][4];
#pragma unroll
    for (int mt = 0; mt < 4; mt++)
#pragma unroll
        for (int nt = 0; nt < 10; nt++)
#pragma unroll
            for (int q = 0; q < 4; q++) C[mt][nt][q] = 0.f;

    // ---- stage A: g1 = relu(masked @ gen1^T), K=64 = 2 chunks x 4 k8-steps ----
    const float* ArowA = msA + (wm * 64 + g) * 68 + tg;
#pragma unroll
    for (int ck = 0; ck < 2; ck++) {
        CP_WAIT_ALL();
        __syncthreads();
        if (ck == 0) issue_chunk40(g_g1F + 10240, bbuf + 10240, tid);
        else         issue_chunk40(g_g2Fb, bbuf, tid);   // stage B chunk 0, overlaps A's last mmas
        const float* bb = bbuf + ck * 10240 + (wn * 10 * 32 + lane) * 2;
#pragma unroll
        for (int kt = 0; kt < 4; kt++) {
            const int ks = ck * 4 + kt;
            uint32_t b0[10], b1[10];
#pragma unroll
            for (int nt = 0; nt < 10; nt++) {
                float2 bv = *(const float2*)(bb + kt * 2560 + nt * 64);
                b0[nt] = __float_as_uint(bv.x);
                b1[nt] = __float_as_uint(bv.y);
            }
#pragma unroll
            for (int mt = 0; mt < 4; mt++) {
                const float* ap = ArowA + mt * 16 * 68 + ks * 8;
                uint32_t a0 = __float_as_uint(ap[0]);
                uint32_t a1 = __float_as_uint(ap[8 * 68]);
                uint32_t a2 = __float_as_uint(ap[4]);
                uint32_t a3 = __float_as_uint(ap[8 * 68 + 4]);
#pragma unroll
                for (int nt = 0; nt < 10; nt++)
                    mma_tf32(C[mt][nt], a0, a1, a2, a3, b0[nt], b1[nt]);
            }
        }
    }

    // ---- relu + bf16 pack g1 into g1s (stride 328 halves) ----
#pragma unroll
    for (int mt = 0; mt < 4; mt++) {
        int rL = wm * 64 + mt * 16 + g;
#pragma unroll
        for (int nt = 0; nt < 10; nt++) {
            int n0 = wn * 80 + nt * 8 + 2 * tg;
            uint32_t pL = pack_bf16x2(fmaxf(C[mt][nt][1], 0.f), fmaxf(C[mt][nt][0], 0.f));
            uint32_t pH = pack_bf16x2(fmaxf(C[mt][nt][3], 0.f), fmaxf(C[mt][nt][2], 0.f));
            *(uint32_t*)&g1s[rL * 328 + n0] = pL;
            *(uint32_t*)&g1s[(rL + 8) * 328 + n0] = pH;
        }
    }

#pragma unroll
    for (int mt = 0; mt < 4; mt++)
#pragma unroll
        for (int nt = 0; nt < 10; nt++)
#pragma unroll
            for (int q = 0; q < 4; q++) C[mt][nt][q] = 0.f;

    // ---- stage B: g2 = relu(g1 @ gen2^T + b) . head_w, K=320 = 5 chunks x 4 k16-steps ----
    const int arow_base = (wm * 64 + g) * 328;
    for (int ck = 0; ck < 5; ck++) {
        CP_WAIT_ALL();
        __syncthreads();   // chunk ck visible to all; prior reads of other buffer done; g1s ready (ck=0)
        if (ck < 4) issue_chunk40(g_g2Fb + (ck + 1) * 10240, bbuf + ((ck + 1) & 1) * 10240, tid);
        const uint32_t* bb = (const uint32_t*)(bbuf + (ck & 1) * 10240) + (wn * 10 * 32 + lane) * 2;
#pragma unroll
        for (int kt = 0; kt < 4; kt++) {
            const int colb = (ck * 4 + kt) * 16 + 2 * tg;
            uint32_t b0[10], b1[10];
#pragma unroll
            for (int nt = 0; nt < 10; nt++) {
                uint2 bv = *(const uint2*)(bb + kt * 2560 + nt * 64);
                b0[nt] = bv.x; b1[nt] = bv.y;
            }
#pragma unroll
            for (int mt = 0; mt < 4; mt++) {
                const uint16_t* ap = g1s + arow_base + mt * 16 * 328 + colb;
                uint32_t a0 = *(const uint32_t*)(ap);
                uint32_t a1 = *(const uint32_t*)(ap + 8 * 328);
                uint32_t a2 = *(const uint32_t*)(ap + 8);
                uint32_t a3 = *(const uint32_t*)(ap + 8 * 328 + 8);
#pragma unroll
                for (int nt = 0; nt < 10; nt++)
                    mma_bf16(C[mt][nt], a0, a1, a2, a3, b0[nt], b1[nt]);
            }
        }
    }

    // ---- fused epilogue: relu(C + bias) . head_w -> partials ----
#pragma unroll
    for (int mt = 0; mt < 4; mt++) {
        int rL = wm * 64 + mt * 16 + g;
        int rH = rL + 8;
        float aL = 0.f, aH = 0.f;
#pragma unroll
        for (int nt = 0; nt < 10; nt++) {
            int n0 = wn * 80 + nt * 8 + 2 * tg;
            float2 bi = *(const float2*)&g_biasp[n0];
            float2 hL = *(const float2*)&g_headp[(d0 + rL) * 320 + n0];
            float2 hH = *(const float2*)&g_headp[(d0 + rH) * 320 + n0];
            aL += fmaxf(C[mt][nt][0] + bi.x, 0.f) * hL.x
                + fmaxf(C[mt][nt][1] + bi.y, 0.f) * hL.y;
            aH += fmaxf(C[mt][nt][2] + bi.x, 0.f) * hH.x
                + fmaxf(C[mt][nt][3] + bi.y, 0.f) * hH.y;
        }
        partial[rL * 17 + wn * 4 + tg] = aL;
        partial[rH * 17 + wn * 4 + tg] = aH;
    }
    __syncthreads();

    if (tid < 128) {
        float s = head_b[d0 + tid];
#pragma unroll
        for (int j = 0; j < 16; j++) s += partial[tid * 17 + j];
        xmean[r0 + tid] = s;
    }
}

// ---------------- launch ----------------
extern "C" void kernel_launch(void* const* d_in, const int* in_sizes, int n_in,
                              void* d_out, int out_size) {
    const float* x      = (const float*)d_in[0];
    const float* eps    = (const float*)d_in[1];
    const float* W      = (const float*)d_in[2];
    const float* enc1_w = (const float*)d_in[3];
    const float* enc1_b = (const float*)d_in[4];
    const float* enc2_w = (const float*)d_in[5];
    const float* enc2_b = (const float*)d_in[6];
    const float* zm_w   = (const float*)d_in[7];
    const float* zm_b   = (const float*)d_in[8];
    const float* zv_w   = (const float*)d_in[9];
    const float* zv_b   = (const float*)d_in[10];
    const float* gen1_w = (const float*)d_in[11];
    const float* gen2_w = (const float*)d_in[12];
    const float* gen2_b = (const float*)d_in[13];
    const float* head_w = (const float*)d_in[14];
    const float* head_b = (const float*)d_in[15];

    float* out   = (float*)d_out;
    float* xmean = out;
    float* z     = out + BD;
    float* zm    = out + BD + Bc * Lc;
    float* zlv   = out + BD + 2 * Bc * Lc;

    {
        int tot = 512 * 320 + 320 * 320 + 320 * 128 + 20480 + 51200 + Dc * 320 + 320;
        prep_kernel<<<(tot + 255) / 256, 256>>>(gen1_w, gen2_w, head_w, gen2_b,
                                                enc1_w, enc2_w, zm_w, zv_w);
    }

    enc_kernel<<<Bc / RPC, 320>>>(x, eps, enc1_b, enc2_b, zm_b, zv_b, zm, zlv, z);

    const int smem_bytes = (20992 + 8704 + 20480 + 2176) * 4;   // 209,408 B
    cudaFuncSetAttribute(decoder_kernel, cudaFuncAttributeMaxDynamicSharedMemorySize,
                         smem_bytes);
    decoder_kernel<<<BD / 128, 256, smem_bytes>>>(W, z, head_b, xmean);
}

// round 13
// speedup vs baseline: 3.8742x; 1.0445x over previous
#include <cuda_runtime.h>
#include <math.h>
#include <stdint.h>

// Shapes: B=256, D=512, L=64, H=300
#define Bc 256
#define Dc 512
#define Lc 64
#define Hc 300
#define BD (Bc*Dc)

// ---------------- device scratch ----------------
__device__ float g_e1T[512 * 320];                 // encoder weights transposed/padded
__device__ float g_e2T[320 * 320];
__device__ float g_zT[320 * 128];
__device__ __align__(16) uint32_t g_g1Fb[10240];   // gen1 bf16 frags: [ks16(4)][nt(40)][lane(32)][2]
__device__ __align__(16) uint32_t g_g2Fb[51200];   // gen2 bf16 frags: [ks16(20)][nt(40)][lane(32)][2]
__device__ float g_headp[Dc * 320];                // head_w padded [d][g]
__device__ float g_biasp[320];                     // gen2_b padded

// ---------------- helpers ----------------
__device__ __forceinline__ uint32_t pack_bf16x2(float hi, float lo) {
    uint32_t d; asm("cvt.rn.bf16x2.f32 %0, %1, %2;" : "=r"(d) : "f"(hi), "f"(lo)); return d;
}
__device__ __forceinline__ uint32_t smem_u32(const void* p) {
    uint32_t a;
    asm("{ .reg .u64 t; cvta.to.shared.u64 t, %1; cvt.u32.u64 %0, t; }" : "=r"(a) : "l"(p));
    return a;
}
__device__ __forceinline__ void mma_bf16(float* c, uint32_t a0, uint32_t a1, uint32_t a2,
                                         uint32_t a3, uint32_t b0, uint32_t b1) {
    asm volatile(
        "mma.sync.aligned.m16n8k16.row.col.f32.bf16.bf16.f32 "
        "{%0,%1,%2,%3}, {%4,%5,%6,%7}, {%8,%9}, {%0,%1,%2,%3};"
        : "+f"(c[0]), "+f"(c[1]), "+f"(c[2]), "+f"(c[3])
        : "r"(a0), "r"(a1), "r"(a2), "r"(a3), "r"(b0), "r"(b1));
}

// ---------------- prep: transpose/pad + round + pack MMA fragments ----------------
__global__ void prep_kernel(const float* __restrict__ g1w, const float* __restrict__ g2w,
                            const float* __restrict__ hw,  const float* __restrict__ g2b,
                            const float* __restrict__ e1w, const float* __restrict__ e2w,
                            const float* __restrict__ zmw, const float* __restrict__ zvw) {
    const int n1 = 512 * 320;            // e1T
    const int n2 = n1 + 320 * 320;       // e2T
    const int n3 = n2 + 320 * 128;       // zT
    const int n4 = n3 + 10240;           // g1Fb (bf16 frags)
    const int n5 = n4 + 51200;           // g2Fb (bf16 frags)
    const int n6 = n5 + Dc * 320;        // headp
    const int n7 = n6 + 320;             // biasp
    int i = blockIdx.x * blockDim.x + threadIdx.x;
    if (i >= n7) return;
    if (i < n1) { int k = i / 320, c = i % 320; g_e1T[i] = (c < Hc) ? e1w[c * Dc + k] : 0.f; }
    else if (i < n2) { int j = i - n1; int k = j / 320, c = j % 320;
        g_e2T[j] = (c < Hc && k < Hc) ? e2w[c * Hc + k] : 0.f; }
    else if (i < n3) { int j = i - n2; int k = j / 128, c = j % 128;
        float v = 0.f; if (k < Hc) v = (c < 64) ? zmw[c * Hc + k] : zvw[(c - 64) * Hc + k];
        g_zT[j] = v; }
    else if (i < n4) { int j = i - n3;
        int ks16 = j / 2560, r = j % 2560;
        int nt = r / 64, r2 = r % 64, lane = r2 >> 1, rr = r2 & 1;
        int g = lane >> 2, tg = lane & 3;
        int k = ks16 * 16 + tg * 2 + rr * 8;    // k in [0,64)
        int n = nt * 8 + g;
        float lo = (n < Hc) ? g1w[n * Lc + k] : 0.f;
        float hi = (n < Hc) ? g1w[n * Lc + k + 1] : 0.f;
        g_g1Fb[j] = pack_bf16x2(hi, lo); }
    else if (i < n5) { int j = i - n4;
        int ks16 = j / 2560, r = j % 2560;
        int nt = r / 64, r2 = r % 64, lane = r2 >> 1, rr = r2 & 1;
        int g = lane >> 2, tg = lane & 3;
        int k = ks16 * 16 + tg * 2 + rr * 8;
        int n = nt * 8 + g;
        float lo = (n < Hc && k < Hc) ? g2w[n * Hc + k] : 0.f;
        float hi = (n < Hc && (k + 1) < Hc) ? g2w[n * Hc + k + 1] : 0.f;
        g_g2Fb[j] = pack_bf16x2(hi, lo); }
    else if (i < n6) { int j = i - n5; int d = j / 320, g = j % 320;
        g_headp[j] = (g < Hc) ? hw[d * Hc + g] : 0.f; }
    else { int g = i - n6; g_biasp[g] = (g < Hc) ? g2b[g] : 0.f; }
}

// ---------------- fused encoder: 4 batch rows per CTA, 320 threads (fp32, exact) ----------------
#define RPC 4
__global__ __launch_bounds__(320)
void enc_kernel(const float* __restrict__ x, const float* __restrict__ eps,
                const float* __restrict__ e1b, const float* __restrict__ e2b,
                const float* __restrict__ zmb, const float* __restrict__ zvb,
                float* __restrict__ zm, float* __restrict__ zlv, float* __restrict__ z) {
    __shared__ float xs[RPC][512];
    __shared__ float h1s[RPC][320];
    __shared__ float h2s[RPC][320];
    __shared__ float zs[RPC][128];
    const int tid = threadIdx.x;
    const int b0 = blockIdx.x * RPC;

    for (int t = tid; t < RPC * 512; t += 320)
        xs[t >> 9][t & 511] = x[(b0 + (t >> 9)) * 512 + (t & 511)];
    __syncthreads();

    const int j = tid;
    {
        float bj = (j < Hc) ? e1b[j] : 0.f;
        float acc[RPC];
#pragma unroll
        for (int r = 0; r < RPC; r++) acc[r] = bj;
#pragma unroll 8
        for (int k = 0; k < 512; k++) {
            float w = g_e1T[k * 320 + j];
#pragma unroll
            for (int r = 0; r < RPC; r++) acc[r] += xs[r][k] * w;
        }
#pragma unroll
        for (int r = 0; r < RPC; r++) h1s[r][j] = fmaxf(acc[r], 0.f);
    }
    __syncthreads();
    {
        float bj = (j < Hc) ? e2b[j] : 0.f;
        float acc[RPC];
#pragma unroll
        for (int r = 0; r < RPC; r++) acc[r] = bj;
#pragma unroll 8
        for (int k = 0; k < 320; k++) {
            float w = g_e2T[k * 320 + j];
#pragma unroll
            for (int r = 0; r < RPC; r++) acc[r] += h1s[r][k] * w;
        }
#pragma unroll
        for (int r = 0; r < RPC; r++) h2s[r][j] = fmaxf(acc[r], 0.f);
    }
    __syncthreads();
    if (j < 128) {
        float bj = (j < 64) ? zmb[j] : zvb[j - 64];
        float acc[RPC];
#pragma unroll
        for (int r = 0; r < RPC; r++) acc[r] = bj;
#pragma unroll 8
        for (int k = 0; k < 320; k++) {
            float w = g_zT[k * 128 + j];
#pragma unroll
            for (int r = 0; r < RPC; r++) acc[r] += h2s[r][k] * w;
        }
#pragma unroll
        for (int r = 0; r < RPC; r++) zs[r][j] = acc[r];
    }
    __syncthreads();
    if (j < 64) {
#pragma unroll
        for (int r = 0; r < RPC; r++) {
            int b = b0 + r;
            float m = zs[r][j], lv = zs[r][j + 64];
            zm[b * 64 + j] = m;
            zlv[b * 64 + j] = lv;
            z[b * 64 + j] = m + eps[b * 64 + j] * expf(0.5f * lv);
        }
    }
}

// ---------------- cp.async: one 40KB chunk (10240 x 4B) = 10 x 16B per thread ----------------
__device__ __forceinline__ void issue_chunk40(const void* src, void* dstp, int tid) {
    const float4* s = (const float4*)src + tid;
    uint32_t d = smem_u32(dstp) + (uint32_t)tid * 16;
#pragma unroll
    for (int j = 0; j < 10; j++) {
        asm volatile("cp.async.cg.shared.global [%0], [%1], 16;"
                     :: "r"(d + j * 256 * 16), "l"(s + j * 256));
    }
    asm volatile("cp.async.commit_group;" ::: "memory");
}
#define CP_WAIT_ALL() asm volatile("cp.async.wait_group 0;" ::: "memory")

// ---------------- fused decoder: all-bf16 mma.sync ----------------
// grid = 1024 CTAs x 256 threads (8 warps, 2m x 4n; warp tile 64x80).
// smem floats: g1s(bf16 128x328 = 20992f) | msA(bf16 128x72 = 4608f) | bbuf(2x10240f) | partial(128x17)
__global__ __launch_bounds__(256, 1)
void decoder_kernel(const float* __restrict__ W, const float* __restrict__ z_all,
                    const float* __restrict__ head_b, float* __restrict__ xmean) {
    extern __shared__ float sm[];
    uint16_t* g1s = (uint16_t*)sm;            // 128 x 328 bf16 (stride 328 halves)
    uint32_t* msA = (uint32_t*)(sm + 20992);  // 128 x 36 u32 (bf16 pairs, stride 36 u32)
    float* bbuf = sm + 20992 + 4608;          // 2 x 10240 floats
    float* partial = bbuf + 20480;            // 128 x 17

    const int tid = threadIdx.x;
    const int lane = tid & 31;
    const int wid = tid >> 5;
    const int wm = wid & 1;
    const int wn = wid >> 1;
    const int g = lane >> 2;
    const int tg = lane & 3;
    const int r0 = blockIdx.x * 128;
    const int b = r0 >> 9;
    const int d0 = r0 & 511;
    const float* zrow = z_all + b * Lc;

    // prefetch stage A weight chunk immediately (overlaps masked fill)
    issue_chunk40(g_g1Fb, bbuf, tid);

    // ---- masked A = bf16(z * W), 128 rows x 32 u32 (stride 36 u32) ----
    for (int t = tid; t < 4096; t += 256) {
        int m = t >> 5, c2 = t & 31;
        float2 w2 = *(const float2*)&W[(d0 + m) * Lc + c2 * 2];
        float2 z2 = *(const float2*)&zrow[c2 * 2];
        msA[m * 36 + c2] = pack_bf16x2(w2.y * z2.y, w2.x * z2.x);
    }

    float C[4][10][4];
#pragma unroll
    for (int mt = 0; mt < 4; mt++)
#pragma unroll
        for (int nt = 0; nt < 10; nt++)
#pragma unroll
            for (int q = 0; q < 4; q++) C[mt][nt][q] = 0.f;

    // ---- stage A: g1 = relu(masked @ gen1^T), K=64 = 4 k16-steps, single chunk ----
    CP_WAIT_ALL();
    __syncthreads();
    issue_chunk40(g_g2Fb, bbuf + 10240, tid);   // stage B chunk 0 -> bbuf1, overlaps A mmas
    {
        const uint32_t* bb = (const uint32_t*)bbuf + (wn * 10 * 32 + lane) * 2;
        const uint32_t* arow = msA + (wm * 64 + g) * 36 + tg;
#pragma unroll
        for (int kt = 0; kt < 4; kt++) {
            uint32_t b0[10], b1[10];
#pragma unroll
            for (int nt = 0; nt < 10; nt++) {
                uint2 bv = *(const uint2*)(bb + kt * 2560 + nt * 64);
                b0[nt] = bv.x; b1[nt] = bv.y;
            }
#pragma unroll
            for (int mt = 0; mt < 4; mt++) {
                const uint32_t* ap = arow + mt * 16 * 36 + kt * 8;
                uint32_t a0 = ap[0];
                uint32_t a1 = ap[8 * 36];
                uint32_t a2 = ap[4];
                uint32_t a3 = ap[8 * 36 + 4];
#pragma unroll
                for (int nt = 0; nt < 10; nt++)
                    mma_bf16(C[mt][nt], a0, a1, a2, a3, b0[nt], b1[nt]);
            }
        }
    }

    // ---- relu + bf16 pack g1 into g1s (stride 328 halves) ----
#pragma unroll
    for (int mt = 0; mt < 4; mt++) {
        int rL = wm * 64 + mt * 16 + g;
#pragma unroll
        for (int nt = 0; nt < 10; nt++) {
            int n0 = wn * 80 + nt * 8 + 2 * tg;
            uint32_t pL = pack_bf16x2(fmaxf(C[mt][nt][1], 0.f), fmaxf(C[mt][nt][0], 0.f));
            uint32_t pH = pack_bf16x2(fmaxf(C[mt][nt][3], 0.f), fmaxf(C[mt][nt][2], 0.f));
            *(uint32_t*)&g1s[rL * 328 + n0] = pL;
            *(uint32_t*)&g1s[(rL + 8) * 328 + n0] = pH;
        }
    }

#pragma unroll
    for (int mt = 0; mt < 4; mt++)
#pragma unroll
        for (int nt = 0; nt < 10; nt++)
#pragma unroll
            for (int q = 0; q < 4; q++) C[mt][nt][q] = 0.f;

    // ---- stage B: K=304 = 19 k16-steps over 5 chunks (4,4,4,4,3); chunk ck -> bbuf[(ck+1)&1] ----
    const int arow_base = (wm * 64 + g) * 328;
    for (int ck = 0; ck < 5; ck++) {
        CP_WAIT_ALL();
        __syncthreads();   // chunk ck visible; prior buffer reads done; g1s ready (ck=0)
        if (ck < 4) issue_chunk40(g_g2Fb + (ck + 1) * 10240, bbuf + (ck & 1) * 10240, tid);
        const uint32_t* bb = (const uint32_t*)(bbuf + ((ck + 1) & 1) * 10240) + (wn * 10 * 32 + lane) * 2;
        const int kmax = (ck == 4) ? 3 : 4;
#pragma unroll
        for (int kt = 0; kt < 4; kt++) {
            if (kt >= kmax) break;
            const int colb = (ck * 4 + kt) * 16 + 2 * tg;
            uint32_t b0[10], b1[10];
#pragma unroll
            for (int nt = 0; nt < 10; nt++) {
                uint2 bv = *(const uint2*)(bb + kt * 2560 + nt * 64);
                b0[nt] = bv.x; b1[nt] = bv.y;
            }
#pragma unroll
            for (int mt = 0; mt < 4; mt++) {
                const uint16_t* ap = g1s + arow_base + mt * 16 * 328 + colb;
                uint32_t a0 = *(const uint32_t*)(ap);
                uint32_t a1 = *(const uint32_t*)(ap + 8 * 328);
                uint32_t a2 = *(const uint32_t*)(ap + 8);
                uint32_t a3 = *(const uint32_t*)(ap + 8 * 328 + 8);
#pragma unroll
                for (int nt = 0; nt < 10; nt++)
                    mma_bf16(C[mt][nt], a0, a1, a2, a3, b0[nt], b1[nt]);
            }
        }
    }

    // ---- fused epilogue: relu(C + bias) . head_w -> partials ----
#pragma unroll
    for (int mt = 0; mt < 4; mt++) {
        int rL = wm * 64 + mt * 16 + g;
        int rH = rL + 8;
        float aL = 0.f, aH = 0.f;
#pragma unroll
        for (int nt = 0; nt < 10; nt++) {
            int n0 = wn * 80 + nt * 8 + 2 * tg;
            float2 bi = *(const float2*)&g_biasp[n0];
            float2 hL = *(const float2*)&g_headp[(d0 + rL) * 320 + n0];
            float2 hH = *(const float2*)&g_headp[(d0 + rH) * 320 + n0];
            aL += fmaxf(C[mt][nt][0] + bi.x, 0.f) * hL.x
                + fmaxf(C[mt][nt][1] + bi.y, 0.f) * hL.y;
            aH += fmaxf(C[mt][nt][2] + bi.x, 0.f) * hH.x
                + fmaxf(C[mt][nt][3] + bi.y, 0.f) * hH.y;
        }
        partial[rL * 17 + wn * 4 + tg] = aL;
        partial[rH * 17 + wn * 4 + tg] = aH;
    }
    __syncthreads();

    if (tid < 128) {
        float s = head_b[d0 + tid];
#pragma unroll
        for (int j = 0; j < 16; j++) s += partial[tid * 17 + j];
        xmean[r0 + tid] = s;
    }
}

// ---------------- launch ----------------
extern "C" void kernel_launch(void* const* d_in, const int* in_sizes, int n_in,
                              void* d_out, int out_size) {
    const float* x      = (const float*)d_in[0];
    const float* eps    = (const float*)d_in[1];
    const float* W      = (const float*)d_in[2];
    const float* enc1_w = (const float*)d_in[3];
    const float* enc1_b = (const float*)d_in[4];
    const float* enc2_w = (const float*)d_in[5];
    const float* enc2_b = (const float*)d_in[6];
    const float* zm_w   = (const float*)d_in[7];
    const float* zm_b   = (const float*)d_in[8];
    const float* zv_w   = (const float*)d_in[9];
    const float* zv_b   = (const float*)d_in[10];
    const float* gen1_w = (const float*)d_in[11];
    const float* gen2_w = (const float*)d_in[12];
    const float* gen2_b = (const float*)d_in[13];
    const float* head_w = (const float*)d_in[14];
    const float* head_b = (const float*)d_in[15];

    float* out   = (float*)d_out;
    float* xmean = out;
    float* z     = out + BD;
    float* zm    = out + BD + Bc * Lc;
    float* zlv   = out + BD + 2 * Bc * Lc;

    {
        int tot = 512 * 320 + 320 * 320 + 320 * 128 + 10240 + 51200 + Dc * 320 + 320;
        prep_kernel<<<(tot + 255) / 256, 256>>>(gen1_w, gen2_w, head_w, gen2_b,
                                                enc1_w, enc2_w, zm_w, zv_w);
    }

    enc_kernel<<<Bc / RPC, 320>>>(x, eps, enc1_b, enc2_b, zm_b, zv_b, zm, zlv, z);

    const int smem_bytes = (20992 + 4608 + 20480 + 2176) * 4;   // 193,024 B
    cudaFuncSetAttribute(decoder_kernel, cudaFuncAttributeMaxDynamicSharedMemorySize,
                         smem_bytes);
    decoder_kernel<<<BD / 128, 256, smem_bytes>>>(W, z, head_b, xmean);
}